// round 17
// baseline (speedup 1.0000x reference)
#include <cuda_runtime.h>
#include <cuda_fp16.h>
#include <cstdint>

#define Bb 32
#define Np 2048
#define NSd 512
#define KN 16
#define NT (Bb*NSd)          // 16384 tiles
#define JJ (NT*KN)           // 262144 columns
#define EPSf 1e-5

// ---------------- scratch ----------------
__device__ float  g_grouped[NT*KN*3];
__device__ double g_sum9[9];
__device__ float  g_Weff2[256*3];
__device__ float  g_A1[256*3];
__device__ float  g_c1v[256];
__device__ float4 g_A1q[256];                  // (a0,a1,a2,c1)
__device__ __half g_Ph [NT*256];               // pooled [tile][c] fp16
__device__ __half g_w3h[512*512];              // fp16 w3
__device__ __half g_w4h[256*512];              // fp16 w4
__device__ float  g_Zp[(size_t)NT*512];        // 32 MB  Zp[t][o] = w3a @ pooled
__device__ __half g_Zh[(size_t)JJ*512];        // 268 MB  [j][c] fp16
__device__ float  g_M4[NT*256];                // max_k conv4-out [tile][o]
__device__ double g_bn3sum[512], g_bn3sq[512], g_bn4sum[256], g_bn4sq[256];
__device__ float  g_a3[512], g_d3[512], g_a4[256], g_d4[256];

// ---------------- helpers ----------------
__device__ __forceinline__ uint32_t smem_u32(const void* p) {
    uint32_t a;
    asm("{ .reg .u64 t; cvta.to.shared.u64 t, %1; cvt.u32.u64 %0, t; }" : "=r"(a) : "l"(p));
    return a;
}
#define LDM4(r0,r1,r2,r3,addr) \
    asm volatile("ldmatrix.sync.aligned.m8n8.x4.shared.b16 {%0,%1,%2,%3}, [%4];" \
        : "=r"(r0),"=r"(r1),"=r"(r2),"=r"(r3) : "r"(addr))
#define MMA16(c, a, b) \
    asm volatile("mma.sync.aligned.m16n8k16.row.col.f32.f16.f16.f32 " \
        "{%0,%1,%2,%3}, {%4,%5,%6,%7}, {%8,%9}, {%0,%1,%2,%3};" \
        : "+f"((c)[0]),"+f"((c)[1]),"+f"((c)[2]),"+f"((c)[3]) \
        : "r"((a)[0]),"r"((a)[1]),"r"((a)[2]),"r"((a)[3]), "r"((b)[0]),"r"((b)[1]))
#define CPA(dst, src) asm volatile("cp.async.cg.shared.global [%0], [%1], 16;" ::"r"(dst),"l"(src))
#define CPA_COMMIT()  asm volatile("cp.async.commit_group;" ::: "memory")
#define CPA_WAIT0()   asm volatile("cp.async.wait_group 0;" ::: "memory")

// ---------------- zero accumulators (graph replays!) ----------------
__global__ void zerok() {
    int t = threadIdx.x;
    if (t < 9) g_sum9[t] = 0.0;
    for (int i = t; i < 512; i += blockDim.x) { g_bn3sum[i] = 0.0; g_bn3sq[i] = 0.0; }
    for (int i = t; i < 256; i += blockDim.x) { g_bn4sum[i] = 0.0; g_bn4sq[i] = 0.0; }
}

__global__ void precompk(const float* __restrict__ w1, const float* __restrict__ w2) {
    int t = threadIdx.x;
    if (t < 256) {
        double s0 = 0.0, s1 = 0.0, s2 = 0.0;
        for (int i = 0; i < 256; i++) {
            double wi = (double)w2[t*256 + i];
            s0 += wi * ((double)w1[i*6+0] + (double)w1[i*6+3]);
            s1 += wi * ((double)w1[i*6+1] + (double)w1[i*6+4]);
            s2 += wi * ((double)w1[i*6+2] + (double)w1[i*6+5]);
        }
        g_Weff2[t*3+0] = (float)s0; g_Weff2[t*3+1] = (float)s1; g_Weff2[t*3+2] = (float)s2;
    }
}

// pre-round weights to fp16
__global__ void roundwk(const float* __restrict__ w3, const float* __restrict__ w4) {
    int i = blockIdx.x*512 + threadIdx.x;
    if (i < 512*512) g_w3h[i] = __float2half_rn(w3[i]);
    if (i < 256*512) g_w4h[i] = __float2half_rn(w4[i]);
}

// ---------------- FPS: 32 blocks x 256 threads, 8 pts/thread, 1 barrier/step ----------------
__global__ void fpsk(const float* __restrict__ p, float* __restrict__ outc) {
    __shared__ float sp[Np*3];
    __shared__ unsigned long long skey[2][8];
    __shared__ int scs[NSd];
    int b = blockIdx.x, t = threadIdx.x;
    for (int i = t; i < Np*3; i += 256) sp[i] = p[b*Np*3 + i];
    __syncthreads();
    float px[8], py[8], pz[8], dist[8];
    #pragma unroll
    for (int i = 0; i < 8; i++) {
        int n = t + 256*i;
        px[i] = sp[n*3+0]; py[i] = sp[n*3+1]; pz[i] = sp[n*3+2];
        dist[i] = 1e10f;
    }
    int lane = t & 31, wid = t >> 5;
    int cs = 0;
    for (int s = 0; s < NSd; s++) {
        if (t == 0) scs[s] = cs;
        float cx = sp[cs*3+0], cy = sp[cs*3+1], cz = sp[cs*3+2];
        unsigned long long best = 0ull;
        #pragma unroll
        for (int i = 0; i < 8; i++) {
            float dx = __fadd_rn(px[i], -cx);
            float dy = __fadd_rn(py[i], -cy);
            float dz = __fadd_rn(pz[i], -cz);
            float d = __fadd_rn(__fadd_rn(__fmul_rn(dx,dx), __fmul_rn(dy,dy)), __fmul_rn(dz,dz));
            dist[i] = fminf(dist[i], d);
            unsigned long long key = ((unsigned long long)__float_as_uint(dist[i]) << 32)
                                   | (unsigned)(Np - 1 - (t + 256*i));
            best = max(best, key);
        }
        #pragma unroll
        for (int off = 16; off; off >>= 1)
            best = max(best, __shfl_down_sync(0xffffffffu, best, off));
        if (lane == 0) skey[s & 1][wid] = best;
        __syncthreads();
        const unsigned long long* sk = skey[s & 1];
        unsigned long long k2 = max(max(max(sk[0], sk[1]), max(sk[2], sk[3])),
                                    max(max(sk[4], sk[5]), max(sk[6], sk[7])));
        cs = Np - 1 - (int)(unsigned)(k2 & 0xffffffffull);
    }
    __syncthreads();
    for (int s = t; s < NSd; s += 256) {
        int idx = scs[s];
        outc[(b*NSd + s)*3 + 0] = sp[idx*3+0];
        outc[(b*NSd + s)*3 + 1] = sp[idx*3+1];
        outc[(b*NSd + s)*3 + 2] = sp[idx*3+2];
    }
}

// ---------------- kNN: 512 blocks x 256 threads; 8 threads per centroid ----------------
#define KNN_SMEM 65536
__global__ void knnk(const float* __restrict__ p, const float* __restrict__ cntrd) {
    extern __shared__ __align__(16) char ksm[];
    float4* shp4 = (float4*)ksm;
    float*  md   = (float*)(ksm + 32768);
    int*    mi   = (int*)(ksm + 49152);
    __shared__ double s9[9];
    int t = threadIdx.x;
    int cl = t >> 3, q = t & 7;
    int gc = blockIdx.x*32 + cl;
    int b = blockIdx.x >> 4;
    for (int n = t; n < Np; n += 256) {
        float x = p[b*Np*3 + n*3 + 0];
        float y = p[b*Np*3 + n*3 + 1];
        float z = p[b*Np*3 + n*3 + 2];
        float p2 = __fadd_rn(__fadd_rn(__fmul_rn(x,x), __fmul_rn(y,y)), __fmul_rn(z,z));
        shp4[n] = make_float4(x, y, z, p2);
    }
    if (t < 9) s9[t] = 0.0;
    __syncthreads();
    float cx = cntrd[gc*3+0], cy = cntrd[gc*3+1], cz = cntrd[gc*3+2];
    float c2 = __fadd_rn(__fadd_rn(__fmul_rn(cx,cx), __fmul_rn(cy,cy)), __fmul_rn(cz,cz));
    float hd[KN]; int hi[KN];
    #pragma unroll
    for (int k = 0; k < KN; k++) { hd[k] = 3.4e38f; hi[k] = 0; }
    int n0 = q*256;
    for (int i = 0; i < 256; i++) {
        int n = n0 + i;
        float4 v = shp4[n];
        float dot = __fadd_rn(__fadd_rn(__fmul_rn(cx, v.x),
                                        __fmul_rn(cy, v.y)),
                              __fmul_rn(cz, v.z));
        float d2 = __fadd_rn(__fadd_rn(c2, v.w), -__fmul_rn(2.0f, dot));
        if (d2 < hd[KN-1]) {
            hd[KN-1] = d2; hi[KN-1] = n;
            #pragma unroll
            for (int j = KN-1; j > 0; --j) {
                bool sw = hd[j] < hd[j-1];
                float td = hd[j]; int ti = hi[j];
                float tdm = hd[j-1]; int tim = hi[j-1];
                hd[j]   = sw ? tdm : td;   hi[j]   = sw ? tim : ti;
                hd[j-1] = sw ? td  : tdm;  hi[j-1] = sw ? ti  : tim;
            }
        }
    }
    int base = (cl*8 + q)*16;
    #pragma unroll
    for (int k = 0; k < KN; k++) { md[base + k] = hd[k]; mi[base + k] = hi[k]; }
    __syncthreads();

    if (q == 0) {
        int lb = cl*128;
        int p0 = 0, p1 = 0, p2 = 0, p3 = 0, p4 = 0, p5 = 0, p6 = 0, p7 = 0;
        double sx=0, sy=0, sz=0, sxx=0, syy=0, szz=0, sxy=0, sxz=0, syz=0;
        #pragma unroll 1
        for (int k = 0; k < KN; k++) {
            float d0 = (p0 < 16) ? md[lb + p0]       : 3.4e38f;
            float d1 = (p1 < 16) ? md[lb + 16 + p1]  : 3.4e38f;
            float d2v= (p2 < 16) ? md[lb + 32 + p2]  : 3.4e38f;
            float d3 = (p3 < 16) ? md[lb + 48 + p3]  : 3.4e38f;
            float d4 = (p4 < 16) ? md[lb + 64 + p4]  : 3.4e38f;
            float d5 = (p5 < 16) ? md[lb + 80 + p5]  : 3.4e38f;
            float d6 = (p6 < 16) ? md[lb + 96 + p6]  : 3.4e38f;
            float d7 = (p7 < 16) ? md[lb + 112 + p7] : 3.4e38f;
            int bq = 0; float bd = d0;
            if (d1 < bd) { bd = d1; bq = 1; }
            if (d2v < bd) { bd = d2v; bq = 2; }
            if (d3 < bd) { bd = d3; bq = 3; }
            if (d4 < bd) { bd = d4; bq = 4; }
            if (d5 < bd) { bd = d5; bq = 5; }
            if (d6 < bd) { bd = d6; bq = 6; }
            if (d7 < bd) { bd = d7; bq = 7; }
            int n;
            if (bq == 0)      { n = mi[lb + p0];       p0++; }
            else if (bq == 1) { n = mi[lb + 16 + p1];  p1++; }
            else if (bq == 2) { n = mi[lb + 32 + p2];  p2++; }
            else if (bq == 3) { n = mi[lb + 48 + p3];  p3++; }
            else if (bq == 4) { n = mi[lb + 64 + p4];  p4++; }
            else if (bq == 5) { n = mi[lb + 80 + p5];  p5++; }
            else if (bq == 6) { n = mi[lb + 96 + p6];  p6++; }
            else              { n = mi[lb + 112 + p7]; p7++; }
            float4 v = shp4[n];
            g_grouped[(gc*KN + k)*3 + 0] = v.x;
            g_grouped[(gc*KN + k)*3 + 1] = v.y;
            g_grouped[(gc*KN + k)*3 + 2] = v.z;
            sx += v.x; sy += v.y; sz += v.z;
            sxx += (double)v.x*v.x; syy += (double)v.y*v.y; szz += (double)v.z*v.z;
            sxy += (double)v.x*v.y; sxz += (double)v.x*v.z; syz += (double)v.y*v.z;
        }
        atomicAdd(&s9[0], sx);  atomicAdd(&s9[1], sy);  atomicAdd(&s9[2], sz);
        atomicAdd(&s9[3], sxx); atomicAdd(&s9[4], syy); atomicAdd(&s9[5], szz);
        atomicAdd(&s9[6], sxy); atomicAdd(&s9[7], sxz); atomicAdd(&s9[8], syz);
    }
    __syncthreads();
    if (t < 9) atomicAdd(&g_sum9[t], s9[t]);
}

// ---------------- BN1 affine from analytic moments ----------------
__global__ void bn1k(const float* __restrict__ b2, const float* __restrict__ g1,
                     const float* __restrict__ b1) {
    int o = threadIdx.x;
    if (o >= 256) return;
    double inv = 1.0 / (double)JJ;
    double Ex = g_sum9[0]*inv, Ey = g_sum9[1]*inv, Ez = g_sum9[2]*inv;
    double Mxx = g_sum9[3]*inv, Myy = g_sum9[4]*inv, Mzz = g_sum9[5]*inv;
    double Mxy = g_sum9[6]*inv, Mxz = g_sum9[7]*inv, Myz = g_sum9[8]*inv;
    double w0 = g_Weff2[o*3], w1v = g_Weff2[o*3+1], w2v = g_Weff2[o*3+2];
    double bo = b2[o];
    double wEg = w0*Ex + w1v*Ey + w2v*Ez;
    double m = wEg + bo;
    double Ex2 = w0*w0*Mxx + w1v*w1v*Myy + w2v*w2v*Mzz
               + 2.0*(w0*w1v*Mxy + w0*w2v*Mxz + w1v*w2v*Myz)
               + 2.0*bo*wEg + bo*bo;
    double var = Ex2 - m*m;
    double s = (double)g1[o] / sqrt(var + EPSf);
    float a0 = (float)(s*w0), a1 = (float)(s*w1v), a2 = (float)(s*w2v);
    float c1 = (float)((double)b1[o] + s*(bo - m));
    g_A1[o*3+0] = a0; g_A1[o*3+1] = a1; g_A1[o*3+2] = a2;
    g_c1v[o] = c1;
    g_A1q[o] = make_float4(a0, a1, a2, c1);
}

// ---------------- pooled: Ph[tile][c] = fp16(max_k relu(A1.xyz + c1)) ----------------
__global__ void pgenk() {
    __shared__ float gsh[48];
    int t = threadIdx.x;
    float a0 = g_A1[t*3], a1 = g_A1[t*3+1], a2 = g_A1[t*3+2], c1 = g_c1v[t];
    for (int it = 0; it < 8; it++) {
        int tile = blockIdx.x*8 + it;
        __syncthreads();
        if (t < 48) gsh[t] = g_grouped[tile*48 + t];
        __syncthreads();
        float mx = 0.0f;
        #pragma unroll
        for (int k = 0; k < KN; k++)
            mx = fmaxf(mx, fmaxf(0.0f, fmaf(a0, gsh[k*3], fmaf(a1, gsh[k*3+1], fmaf(a2, gsh[k*3+2], c1)))));
        g_Ph[(size_t)tile*256 + t] = __float2half_rn(mx);
    }
}

// ================= GEMM0 (fp16): Zp[t][o] = sum_{c<256} w3[o][c]*pooled[t][c] =================
#define G0_SMEM 69120
__global__ __launch_bounds__(256, 2) void tcg0() {
    extern __shared__ __align__(16) char smc[];
    float* smf = (float*)smc;
    uint32_t sb = smem_u32(smc);
    int t = threadIdx.x, lane = t & 31, wid = t >> 5;
    int wm = wid & 3, wn = wid >> 2;
    int t0 = blockIdx.x * 128, o0 = blockIdx.y * 128;

    float acc[2][8][4];
    #pragma unroll
    for (int mf = 0; mf < 2; mf++)
        #pragma unroll
        for (int nf = 0; nf < 8; nf++)
            #pragma unroll
            for (int e = 0; e < 4; e++) acc[mf][nf][e] = 0.0f;

    auto issue = [&](int buf, int kc) {
        uint32_t abb = sb + buf*16384;
        uint32_t bbb = sb + 32768 + buf*16384;
        #pragma unroll
        for (int i = 0; i < 4; i++) {
            int slot = t + 256*i; int o = slot >> 3, chR = slot & 7;
            CPA(abb + o*128 + ((chR ^ (o & 7)) << 4),
                &g_w3h[(size_t)(o0+o)*512 + kc*64 + chR*8]);
        }
        #pragma unroll
        for (int i = 0; i < 4; i++) {
            int slot = t + 256*i; int j = slot >> 3, chR = slot & 7;
            CPA(bbb + j*128 + ((chR ^ (j & 7)) << 4),
                &g_Ph[(size_t)(t0 + j)*256 + kc*64 + chR*8]);
        }
        CPA_COMMIT();
    };

    auto compute = [&](int buf) {
        uint32_t abase = sb + buf*16384;
        uint32_t bbase = sb + 32768 + buf*16384;
        int t7 = lane & 7, mi = lane >> 3;
        #pragma unroll
        for (int s = 0; s < 4; s++) {
            uint32_t a[2][4], b[8][2];
            #pragma unroll
            for (int mf = 0; mf < 2; mf++) {
                int row = wm*32 + mf*16 + ((mi & 1) << 3) + t7;
                int ch = 2*s + (mi >> 1);
                LDM4(a[mf][0], a[mf][1], a[mf][2], a[mf][3],
                     abase + row*128 + ((ch ^ (row & 7)) << 4));
            }
            #pragma unroll
            for (int np = 0; np < 4; np++) {
                int row = wn*64 + np*16 + ((mi >> 1) << 3) + t7;
                int ch = 2*s + (mi & 1);
                LDM4(b[2*np][0], b[2*np][1], b[2*np+1][0], b[2*np+1][1],
                     bbase + row*128 + ((ch ^ (row & 7)) << 4));
            }
            #pragma unroll
            for (int mf = 0; mf < 2; mf++)
                #pragma unroll
                for (int nf = 0; nf < 8; nf++)
                    MMA16(acc[mf][nf], a[mf], b[nf]);
        }
    };

    issue(0, 0);
    for (int kc = 0; kc < 4; kc++) {
        int cur = kc & 1;
        CPA_WAIT0();
        __syncthreads();
        if (kc < 3) issue(cur ^ 1, kc + 1);
        compute(cur);
    }
    __syncthreads();

    int t4 = lane & 3, gr = lane >> 2;
    float* T = smf;
    #pragma unroll
    for (int mf = 0; mf < 2; mf++)
        #pragma unroll
        for (int nf = 0; nf < 8; nf++) {
            int orw = wm*32 + mf*16 + gr;
            int jl = wn*64 + nf*8 + 2*t4;
            T[jl*132 + orw]       = acc[mf][nf][0];
            T[(jl+1)*132 + orw]   = acc[mf][nf][1];
            T[jl*132 + orw + 8]   = acc[mf][nf][2];
            T[(jl+1)*132 + orw+8] = acc[mf][nf][3];
        }
    __syncthreads();
    int col4 = t & 31, wrow = t >> 5;
    #pragma unroll
    for (int r = 0; r < 16; r++) {
        int row = wrow + 8*r;
        float4 v = *(float4*)&T[row*132 + col4*4];
        *(float4*)&g_Zp[(size_t)(t0+row)*512 + o0 + col4*4] = v;
    }
}

// ================= GEMM1 (fp16): Z[j][o] = Zp[t(j)][o] + sum_c w3b[o][c]*H[j][c] =================
// Packed-param H-gen fill: float4 A1q + float4 XYZ, half2 cvt.
#define G1_SMEM 75776
__global__ __launch_bounds__(256, 2) void tcg1() {
    extern __shared__ __align__(16) char smc[];
    float* smf = (float*)smc;
    uint32_t sb = smem_u32(smc);
    int t = threadIdx.x, lane = t & 31, wid = t >> 5;
    int wm = wid & 3, wn = wid >> 2;
    int j0 = blockIdx.x * 128, o0 = blockIdx.y * 128;
    float4* sXYZ4 = (float4*)(smc + 65536);    // 128 x float4 = 2048
    float4* sA1q  = (float4*)(smc + 67584);    // 256 x float4 = 4096
    float*  zpS   = (float*)(smc + 71680);     // 4096

    if (t < 128) {
        int j = j0 + t;
        sXYZ4[t] = make_float4(g_grouped[j*3], g_grouped[j*3+1], g_grouped[j*3+2], 0.f);
    }
    sA1q[t] = g_A1q[t];

    float acc[2][8][4];
    #pragma unroll
    for (int mf = 0; mf < 2; mf++)
        #pragma unroll
        for (int nf = 0; nf < 8; nf++)
            #pragma unroll
            for (int e = 0; e < 4; e++) acc[mf][nf][e] = 0.0f;

    int chR = t & 7, jb = t >> 3;

    auto issue = [&](int buf, int kc) {
        uint32_t abb = sb + buf*16384;
        #pragma unroll
        for (int i = 0; i < 4; i++) {
            int slot = t + 256*i; int o = slot >> 3, cR = slot & 7;
            CPA(abb + o*128 + ((cR ^ (o & 7)) << 4),
                &g_w3h[(size_t)(o0+o)*512 + 256 + kc*64 + cR*8]);
        }
        char* Bp = smc + 32768 + buf*16384;
        int cB = kc*64 + chR*8;
        #pragma unroll
        for (int i = 0; i < 4; i++) {
            int j = jb + 32*i;
            float4 xyz = sXYZ4[j];
            __half hv[8];
            #pragma unroll
            for (int e2 = 0; e2 < 4; e2++) {
                float4 p0 = sA1q[cB + 2*e2];
                float4 p1 = sA1q[cB + 2*e2 + 1];
                float v0 = fmaxf(0.f, fmaf(p0.x, xyz.x, fmaf(p0.y, xyz.y, fmaf(p0.z, xyz.z, p0.w))));
                float v1 = fmaxf(0.f, fmaf(p1.x, xyz.x, fmaf(p1.y, xyz.y, fmaf(p1.z, xyz.z, p1.w))));
                *(__half2*)&hv[2*e2] = __floats2half2_rn(v0, v1);
            }
            *(uint4*)(Bp + j*128 + ((chR ^ (j & 7)) << 4)) = *(uint4*)hv;
        }
        CPA_COMMIT();
    };

    auto compute = [&](int buf) {
        uint32_t abase = sb + buf*16384;
        uint32_t bbase = sb + 32768 + buf*16384;
        int t7 = lane & 7, mi = lane >> 3;
        #pragma unroll
        for (int s = 0; s < 4; s++) {
            uint32_t a[2][4], b[8][2];
            #pragma unroll
            for (int mf = 0; mf < 2; mf++) {
                int row = wm*32 + mf*16 + ((mi & 1) << 3) + t7;
                int ch = 2*s + (mi >> 1);
                LDM4(a[mf][0], a[mf][1], a[mf][2], a[mf][3],
                     abase + row*128 + ((ch ^ (row & 7)) << 4));
            }
            #pragma unroll
            for (int np = 0; np < 4; np++) {
                int row = wn*64 + np*16 + ((mi >> 1) << 3) + t7;
                int ch = 2*s + (mi & 1);
                LDM4(b[2*np][0], b[2*np][1], b[2*np+1][0], b[2*np+1][1],
                     bbase + row*128 + ((ch ^ (row & 7)) << 4));
            }
            #pragma unroll
            for (int mf = 0; mf < 2; mf++)
                #pragma unroll
                for (int nf = 0; nf < 8; nf++)
                    MMA16(acc[mf][nf], a[mf], b[nf]);
        }
    };

    __syncthreads();                // sXYZ4 / sA1q visible
    issue(0, 0);
    for (int kc = 0; kc < 4; kc++) {
        int cur = kc & 1;
        CPA_WAIT0();
        __syncthreads();
        if (kc < 3) issue(cur ^ 1, kc + 1);
        compute(cur);
    }
    __syncthreads();

    {
        int tb = j0 >> 4;
        int tl = t >> 5, ol = (t & 31) * 4;
        float4 v = *(const float4*)&g_Zp[(size_t)(tb + tl)*512 + o0 + ol];
        *(float4*)&zpS[tl*128 + ol] = v;
    }
    __syncthreads();

    int t4 = lane & 3, gr = lane >> 2;
    #pragma unroll
    for (int mf = 0; mf < 2; mf++) {
        int orw = wm*32 + mf*16 + gr;
        #pragma unroll
        for (int nf = 0; nf < 8; nf++) {
            int tl = wn*4 + (nf >> 1);
            float zp0 = zpS[tl*128 + orw];
            float zp1 = zpS[tl*128 + orw + 8];
            acc[mf][nf][0] += zp0; acc[mf][nf][1] += zp0;
            acc[mf][nf][2] += zp1; acc[mf][nf][3] += zp1;
        }
    }

    #pragma unroll
    for (int mf = 0; mf < 2; mf++)
        #pragma unroll
        for (int rs = 0; rs < 2; rs++) {
            double s = 0.0, q = 0.0;
            #pragma unroll
            for (int nf = 0; nf < 8; nf++) {
                float v0 = acc[mf][nf][rs*2], v1 = acc[mf][nf][rs*2+1];
                s += (double)v0 + (double)v1;
                q += (double)v0*(double)v0 + (double)v1*(double)v1;
            }
            s += __shfl_xor_sync(0xffffffffu, s, 1); s += __shfl_xor_sync(0xffffffffu, s, 2);
            q += __shfl_xor_sync(0xffffffffu, q, 1); q += __shfl_xor_sync(0xffffffffu, q, 2);
            if (t4 == 0) {
                int o = o0 + wm*32 + mf*16 + rs*8 + gr;
                atomicAdd(&g_bn3sum[o], s); atomicAdd(&g_bn3sq[o], q);
            }
        }

    float* T = smf;
    #pragma unroll
    for (int mf = 0; mf < 2; mf++)
        #pragma unroll
        for (int nf = 0; nf < 8; nf++) {
            int orw = wm*32 + mf*16 + gr;
            int jl = wn*64 + nf*8 + 2*t4;
            T[jl*132 + orw]       = acc[mf][nf][0];
            T[(jl+1)*132 + orw]   = acc[mf][nf][1];
            T[jl*132 + orw + 8]   = acc[mf][nf][2];
            T[(jl+1)*132 + orw+8] = acc[mf][nf][3];
        }
    __syncthreads();
    int cg16 = t & 15, rr = t >> 4;
    #pragma unroll
    for (int r = 0; r < 8; r++) {
        int row = rr + 16*r;
        float4 v0 = *(float4*)&T[row*132 + cg16*8];
        float4 v1 = *(float4*)&T[row*132 + cg16*8 + 4];
        __half2 h[4];
        h[0] = __floats2half2_rn(v0.x, v0.y);
        h[1] = __floats2half2_rn(v0.z, v0.w);
        h[2] = __floats2half2_rn(v1.x, v1.y);
        h[3] = __floats2half2_rn(v1.z, v1.w);
        *(uint4*)&g_Zh[(size_t)(j0+row)*512 + o0 + cg16*8] = *(uint4*)h;
    }
}

// ================= GEMM2 (fp16): stats + max_k of w4 @ relu(bn3(Z)), half2 BN fill =================
#define G2_SMEM 86016
__global__ __launch_bounds__(256, 2) void tcg2() {
    extern __shared__ __align__(16) char smc[];
    uint32_t sb = smem_u32(smc);
    int t = threadIdx.x, lane = t & 31, wid = t >> 5;
    int wm = wid & 3, wn = wid >> 2;
    int j0 = blockIdx.x * 64;
    __half2* sa3h = (__half2*)(smc + 81920);   // 256 half2 = 1KB
    __half2* sd3h = (__half2*)(smc + 83968);   // 1KB
    sa3h[t] = __floats2half2_rn(g_a3[2*t], g_a3[2*t+1]);
    sd3h[t] = __floats2half2_rn(g_d3[2*t], g_d3[2*t+1]);

    float acc[4][4][4];
    #pragma unroll
    for (int mf = 0; mf < 4; mf++)
        #pragma unroll
        for (int nf = 0; nf < 4; nf++)
            #pragma unroll
            for (int e = 0; e < 4; e++) acc[mf][nf][e] = 0.0f;

    int chR = t & 7, jb = t >> 3;
    const __half2 zero2 = __floats2half2_rn(0.f, 0.f);

    auto issueA = [&](int buf, int kc) {
        uint32_t abb = sb + buf*32768;
        #pragma unroll
        for (int i = 0; i < 8; i++) {
            int slot = t + 256*i; int o = slot >> 3, cR = slot & 7;
            CPA(abb + o*128 + ((cR ^ (o & 7)) << 4),
                &g_w4h[(size_t)o*512 + kc*64 + cR*8]);
        }
        CPA_COMMIT();
    };
    auto loadB = [&](int kc, uint4* br) {
        #pragma unroll
        for (int i = 0; i < 2; i++) {
            int j = jb + 32*i;
            br[i] = *(const uint4*)&g_Zh[(size_t)(j0+j)*512 + kc*64 + chR*8];
        }
    };
    auto storeB = [&](int buf, int kc, const uint4* br) {
        char* Bp = smc + 65536 + buf*8192;
        int cH = kc*32 + chR*4;
        uint4 au = *(uint4*)&sa3h[cH];
        uint4 du = *(uint4*)&sd3h[cH];
        const __half2* ah = (const __half2*)&au;
        const __half2* dh = (const __half2*)&du;
        #pragma unroll
        for (int i = 0; i < 2; i++) {
            int j = jb + 32*i;
            const __half2* hz = (const __half2*)&br[i];
            __half2 v[4];
            #pragma unroll
            for (int e2 = 0; e2 < 4; e2++)
                v[e2] = __hmax2(__hfma2(hz[e2], ah[e2], dh[e2]), zero2);
            *(uint4*)(Bp + j*128 + ((chR ^ (j & 7)) << 4)) = *(uint4*)v;
        }
    };
    auto compute = [&](int buf) {
        uint32_t abase = sb + buf*32768;
        uint32_t bbase = sb + 65536 + buf*8192;
        int t7 = lane & 7, mi = lane >> 3;
        #pragma unroll
        for (int s = 0; s < 4; s++) {
            uint32_t a[4][4], b[4][2];
            #pragma unroll
            for (int mf = 0; mf < 4; mf++) {
                int row = wm*64 + mf*16 + ((mi & 1) << 3) + t7;
                int ch = 2*s + (mi >> 1);
                LDM4(a[mf][0], a[mf][1], a[mf][2], a[mf][3],
                     abase + row*128 + ((ch ^ (row & 7)) << 4));
            }
            #pragma unroll
            for (int np = 0; np < 2; np++) {
                int row = wn*32 + np*16 + ((mi >> 1) << 3) + t7;
                int ch = 2*s + (mi & 1);
                LDM4(b[2*np][0], b[2*np][1], b[2*np+1][0], b[2*np+1][1],
                     bbase + row*128 + ((ch ^ (row & 7)) << 4));
            }
            #pragma unroll
            for (int mf = 0; mf < 4; mf++)
                #pragma unroll
                for (int nf = 0; nf < 4; nf++)
                    MMA16(acc[mf][nf], a[mf], b[nf]);
        }
    };

    __syncthreads();               // sa3h/sd3h visible
    issueA(0, 0);
    {
        uint4 br0[2];
        loadB(0, br0);
        storeB(0, 0, br0);
    }
    uint4 br[2];
    for (int kc = 0; kc < 8; kc++) {
        int cur = kc & 1;
        CPA_WAIT0();
        __syncthreads();
        if (kc < 7) { issueA(cur ^ 1, kc + 1); loadB(kc + 1, br); }
        compute(cur);
        if (kc < 7) storeB(cur ^ 1, kc + 1, br);
    }

    int t4 = lane & 3, gr = lane >> 2;
    int jt0 = (j0 >> 4) + wn*2;
    #pragma unroll
    for (int mf = 0; mf < 4; mf++)
        #pragma unroll
        for (int rs = 0; rs < 2; rs++) {
            int o = wm*64 + mf*16 + rs*8 + gr;
            double s = 0.0, q = 0.0;
            #pragma unroll
            for (int nf = 0; nf < 4; nf++) {
                float v0 = acc[mf][nf][rs*2], v1 = acc[mf][nf][rs*2+1];
                s += (double)v0 + (double)v1;
                q += (double)v0*(double)v0 + (double)v1*(double)v1;
            }
            s += __shfl_xor_sync(0xffffffffu, s, 1); s += __shfl_xor_sync(0xffffffffu, s, 2);
            q += __shfl_xor_sync(0xffffffffu, q, 1); q += __shfl_xor_sync(0xffffffffu, q, 2);
            if (t4 == 0) { atomicAdd(&g_bn4sum[o], s); atomicAdd(&g_bn4sq[o], q); }
            #pragma unroll
            for (int tt = 0; tt < 2; tt++) {
                float m = fmaxf(fmaxf(acc[mf][2*tt][rs*2], acc[mf][2*tt][rs*2+1]),
                                fmaxf(acc[mf][2*tt+1][rs*2], acc[mf][2*tt+1][rs*2+1]));
                m = fmaxf(m, __shfl_xor_sync(0xffffffffu, m, 1));
                m = fmaxf(m, __shfl_xor_sync(0xffffffffu, m, 2));
                if (t4 == 0) g_M4[(size_t)(jt0 + tt)*256 + o] = m;
            }
        }
}

// ---------------- BN affine params ----------------
__global__ void bn3aff(const float* __restrict__ g, const float* __restrict__ b) {
    int c = threadIdx.x;
    if (c >= 512) return;
    double inv = 1.0 / (double)JJ;
    double m = g_bn3sum[c]*inv;
    double var = g_bn3sq[c]*inv - m*m;
    float a = (float)((double)g[c] / sqrt(var + EPSf));
    g_a3[c] = a;
    g_d3[c] = b[c] - (float)m * a;
}
__global__ void bn4aff(const float* __restrict__ g, const float* __restrict__ b) {
    int c = threadIdx.x;
    if (c >= 256) return;
    double inv = 1.0 / (double)JJ;
    double m = g_bn4sum[c]*inv;
    double var = g_bn4sq[c]*inv - m*m;
    float a = (float)((double)g[c] / sqrt(var + EPSf));
    g_a4[c] = a;
    g_d4[c] = b[c] - (float)m * a;
}

// ---------------- final: feat[b][o][ns] = relu(a4*M4 + d4)  (a4>0) ----------------
__global__ void finalk(float* __restrict__ out) {
    __shared__ float sm[32*257];
    int b = blockIdx.x >> 4, chunk = blockIdx.x & 15, t = threadIdx.x;
    int tile0 = b*512 + chunk*32;
    for (int i = t; i < 8192; i += 256) {
        int tl = i >> 8, o = i & 255;
        sm[tl*257 + o] = g_M4[(size_t)(tile0 + tl)*256 + o];
    }
    __syncthreads();
    int nsl = t & 31, og = t >> 5;
    for (int pass = 0; pass < 32; pass++) {
        int o = pass*8 + og;
        float a = g_a4[o], d = g_d4[o];
        float v = fmaxf(0.0f, fmaf(sm[nsl*257 + o], a, d));
        out[Bb*NSd*3 + b*131072 + o*512 + chunk*32 + nsl] = v;
    }
}

// ---------------- launch ----------------
extern "C" void kernel_launch(void* const* d_in, const int* in_sizes, int n_in,
                              void* d_out, int out_size) {
    const float* p    = (const float*)d_in[0];
    const float* w1   = (const float*)d_in[1];
    const float* w2   = (const float*)d_in[2];
    const float* b2   = (const float*)d_in[3];
    const float* bn1g = (const float*)d_in[4];
    const float* bn1b = (const float*)d_in[5];
    const float* w3   = (const float*)d_in[6];
    const float* bn3g = (const float*)d_in[7];
    const float* bn3b = (const float*)d_in[8];
    const float* w4   = (const float*)d_in[9];
    const float* bn4g = (const float*)d_in[10];
    const float* bn4b = (const float*)d_in[11];
    float* out = (float*)d_out;

    cudaFuncSetAttribute(knnk, cudaFuncAttributeMaxDynamicSharedMemorySize, KNN_SMEM);
    cudaFuncSetAttribute(tcg0, cudaFuncAttributeMaxDynamicSharedMemorySize, G0_SMEM);
    cudaFuncSetAttribute(tcg1, cudaFuncAttributeMaxDynamicSharedMemorySize, G1_SMEM);
    cudaFuncSetAttribute(tcg2, cudaFuncAttributeMaxDynamicSharedMemorySize, G2_SMEM);

    zerok<<<1, 512>>>();
    precompk<<<1, 256>>>(w1, w2);
    fpsk<<<32, 256>>>(p, out);                 // centroids -> out[0:49152]
    knnk<<<512, 256, KNN_SMEM>>>(p, out);
    roundwk<<<512, 512>>>(w3, w4);
    bn1k<<<1, 256>>>(b2, bn1g, bn1b);
    pgenk<<<NT/8, 256>>>();
    tcg0<<<dim3(NT/128, 4), 256, G0_SMEM>>>();
    tcg1<<<dim3(JJ/128, 4), 256, G1_SMEM>>>();
    bn3aff<<<1, 512>>>(bn3g, bn3b);
    tcg2<<<JJ/64, 256, G2_SMEM>>>();
    bn4aff<<<1, 256>>>(bn4g, bn4b);
    finalk<<<Bb*16, 256>>>(out);
}